// round 4
// baseline (speedup 1.0000x reference)
#include <cuda_runtime.h>
#include <cuda_fp16.h>
#include <cuda_fp8.h>
#include <stdint.h>

#define N_ENT 4096
#define FDIM  512
#define CELLS 39
#define PAIRS 8192

// ---------------- scratch (device globals: allocation-free rule) ----------------
__device__ __half   g_E16[N_ENT * FDIM];                   // 4 MB   fp16(E)
__device__ uint8_t  g_E8[N_ENT * FDIM * 2];                // 4 MB   [El*2^11 | E] fp8, K=1024 rows
__device__ __half   g_B16[CELLS * FDIM * FDIM];            // 20 MB  [c][kout][n] fp16(64*wl*W)
__device__ uint8_t  g_B8[(size_t)CELLS * FDIM * FDIM * 2]; // 20 MB  [c][kout][Bq | Bl*2^11]
__device__ float    g_T[(size_t)CELLS * N_ENT * FDIM];     // 327 MB T'_c

// ---------------- small helpers ----------------
__device__ __forceinline__ uint32_t smem_to_u32(const void* p) {
    uint32_t a;
    asm("{ .reg .u64 t; cvta.to.shared.u64 t, %1; cvt.u32.u64 %0, t; }" : "=r"(a) : "l"(p));
    return a;
}
__device__ __forceinline__ void cp_async16(uint32_t dst, const void* src) {
    asm volatile("cp.async.cg.shared.global [%0], [%1], 16;" :: "r"(dst), "l"(src));
}
#define CP_COMMIT() asm volatile("cp.async.commit_group;" ::: "memory")
#define CP_WAIT(n)  asm volatile("cp.async.wait_group %0;" :: "n"(n) : "memory")

#define LDSM_X4(r, addr) \
    asm volatile("ldmatrix.sync.aligned.m8n8.x4.shared.b16 {%0,%1,%2,%3}, [%4];" \
        : "=r"((r)[0]), "=r"((r)[1]), "=r"((r)[2]), "=r"((r)[3]) : "r"(addr))

__device__ __forceinline__ void mma_f16(float* c, const uint32_t* a, uint32_t b0, uint32_t b1) {
    asm volatile("mma.sync.aligned.m16n8k16.row.col.f32.f16.f16.f32 "
                 "{%0,%1,%2,%3}, {%4,%5,%6,%7}, {%8,%9}, {%0,%1,%2,%3};"
                 : "+f"(c[0]), "+f"(c[1]), "+f"(c[2]), "+f"(c[3])
                 : "r"(a[0]), "r"(a[1]), "r"(a[2]), "r"(a[3]), "r"(b0), "r"(b1));
}
__device__ __forceinline__ void mma_fp8(float* c, const uint32_t* a, uint32_t b0, uint32_t b1) {
    asm volatile("mma.sync.aligned.m16n8k32.row.col.f32.e4m3.e4m3.f32 "
                 "{%0,%1,%2,%3}, {%4,%5,%6,%7}, {%8,%9}, {%0,%1,%2,%3};"
                 : "+f"(c[0]), "+f"(c[1]), "+f"(c[2]), "+f"(c[3])
                 : "r"(a[0]), "r"(a[1]), "r"(a[2]), "r"(a[3]), "r"(b0), "r"(b1));
}

__device__ __forceinline__ uint8_t to_fp8(float x) {
    return (uint8_t)__nv_cvt_float_to_fp8(x, __NV_SATFINITE, __NV_E4M3);
}

// ---------------- prep kernels ----------------
__global__ void prep_E(const float* __restrict__ emb) {
    for (int i = blockIdx.x * blockDim.x + threadIdx.x; i < N_ENT * FDIM; i += gridDim.x * blockDim.x) {
        float x = emb[i];
        __half h = __float2half(x);
        float lo = (x - __half2float(h)) * 2048.f;   // * 2^11
        g_E16[i] = h;
        int row = i >> 9, col = i & 511;
        g_E8[(size_t)row * 1024 + col]       = to_fp8(lo);   // El*2^11 (k 0..511)
        g_E8[(size_t)row * 1024 + 512 + col] = to_fp8(x);    // E      (k 512..1023)
    }
}

// B = 64 * wl[c,n] * W[n,kout], transposed to [kout][n] via smem tile.
__global__ void prep_B(const float* __restrict__ W, const float* __restrict__ wl) {
    __shared__ float sW[32][33];
    int tx = threadIdx.x, ty = threadIdx.y;
    int n0 = blockIdx.x * 32, k0 = blockIdx.y * 32;
    sW[ty][tx] = W[(n0 + ty) * FDIM + (k0 + tx)];   // coalesced read
    __syncthreads();
    float wv = sW[tx][ty];                           // = W[n0+tx][k0+ty]
    int kout = k0 + ty, n = n0 + tx;
    for (int c = 0; c < CELLS; c++) {
        float v = 64.f * wl[c * FDIM + n] * wv;
        __half h = __float2half(v);
        float lo = (v - __half2float(h)) * 2048.f;
        g_B16[(size_t)c * FDIM * FDIM + kout * FDIM + n] = h;
        size_t b8row = ((size_t)c * FDIM + kout) * 1024;
        g_B8[b8row + n]       = to_fp8(v);    // Bq  (pairs with El)
        g_B8[b8row + 512 + n] = to_fp8(lo);   // Bl*2^11 (pairs with E)
    }
}

// ---------------- GEMM: T'_c = (E @ Wc) * wl[c,:], fp16 main + fp8 corrections ----------------
// CTA tile M=128, N=128, 8 warps (2x4), warp tile 64x32.
// 4 smem tiles per chunk, each 128 rows x 128B (+16B pad): A16, A8, B16, B8.
// Chunk = 128 bytes of K per row: fp16 -> k64, fp8 -> k128. 8 chunks cover both.
#define NKC         8
#define ROW_S       144
#define TILE_BYTES  (128 * ROW_S)     // 18432
#define T_A16       0
#define T_A8        (1 * TILE_BYTES)
#define T_B16       (2 * TILE_BYTES)
#define T_B8        (3 * TILE_BYTES)
#define BUF_BYTES   (4 * TILE_BYTES)  // 73728
#define GEMM_SMEM   (2 * BUF_BYTES)   // 147456

__device__ __forceinline__ void load_buf(uint32_t smem_u, int buf, int kc, int tid,
                                         const char* a16, const char* a8,
                                         const char* b16, const char* b8) {
    const char* srcs[4] = { a16, a8, b16, b8 };
    uint32_t dbase = smem_u + buf * BUF_BYTES;
    #pragma unroll
    for (int t = 0; t < 4; t++) {
        uint32_t dt = dbase + t * TILE_BYTES;
        const char* s = srcs[t] + (size_t)kc * 128;    // all tiles: 128B chunk per row
        #pragma unroll
        for (int i = 0; i < 4; i++) {
            int v = i * 256 + tid;           // 0..1023
            int row = v >> 3, seg = v & 7;   // 128 rows x 8 x 16B
            cp_async16(dt + row * ROW_S + seg * 16,
                       s + (size_t)row * 1024 + seg * 16);   // all rows are 1024B
        }
    }
}

__global__ void __launch_bounds__(256, 1)
gemm_kernel(const float* __restrict__ wl) {
    extern __shared__ char smem[];
    uint32_t smem_u = smem_to_u32(smem);

    const int tid = threadIdx.x;
    const int wid = tid >> 5, lane = tid & 31;
    const int warp_m = wid & 1;
    const int warp_n = wid >> 1;
    const int mt = blockIdx.x, nt = blockIdx.y, c = blockIdx.z;

    const char* a16 = (const char*)g_E16 + (size_t)(mt * 128) * 1024;
    const char* a8  = (const char*)g_E8  + (size_t)(mt * 128) * 1024;
    const char* b16 = (const char*)g_B16 + ((size_t)c * FDIM + nt * 128) * 1024;
    const char* b8  = (const char*)g_B8  + ((size_t)c * FDIM + nt * 128) * 1024;

    float acc[4][4][4];   // fp16 main
    float ac8[4][4][4];   // fp8 corrections (x 2^11 too large)
    #pragma unroll
    for (int i = 0; i < 4; i++)
        #pragma unroll
        for (int j = 0; j < 4; j++)
            #pragma unroll
            for (int q = 0; q < 4; q++) { acc[i][j][q] = 0.f; ac8[i][j][q] = 0.f; }

    const int lr = lane & 15;
    const int lcb = (lane >> 4) * 16;

    load_buf(smem_u, 0, 0, tid, a16, a8, b16, b8);
    CP_COMMIT();

    for (int kc = 0; kc < NKC; kc++) {
        int buf = kc & 1;
        if (kc + 1 < NKC) {
            load_buf(smem_u, buf ^ 1, kc + 1, tid, a16, a8, b16, b8);
            CP_COMMIT();
            CP_WAIT(1);
        } else {
            CP_WAIT(0);
        }
        __syncthreads();

        uint32_t base = smem_u + buf * BUF_BYTES;
        uint32_t a16Row = base + T_A16 + (warp_m * 64 + lr) * ROW_S + lcb;
        uint32_t a8Row  = base + T_A8  + (warp_m * 64 + lr) * ROW_S + lcb;
        uint32_t b16Row = base + T_B16 + (warp_n * 32 + lr) * ROW_S + lcb;
        uint32_t b8Row  = base + T_B8  + (warp_n * 32 + lr) * ROW_S + lcb;

        #pragma unroll
        for (int s = 0; s < 4; s++) {
            uint32_t ko = s * 32;   // 32B: fp16 k16 / fp8 k32 per step
            uint32_t ah[4][4], a8f[4][4], bh[2][4], b8f[2][4];
            #pragma unroll
            for (int mi = 0; mi < 4; mi++) {
                LDSM_X4(ah[mi],  a16Row + mi * (16 * ROW_S) + ko);
                LDSM_X4(a8f[mi], a8Row  + mi * (16 * ROW_S) + ko);
            }
            #pragma unroll
            for (int nj = 0; nj < 2; nj++) {
                LDSM_X4(bh[nj],  b16Row + nj * (16 * ROW_S) + ko);
                LDSM_X4(b8f[nj], b8Row  + nj * (16 * ROW_S) + ko);
            }
            #pragma unroll
            for (int mi = 0; mi < 4; mi++)
                #pragma unroll
                for (int n = 0; n < 4; n++) {
                    int nj = n >> 1, hf = n & 1;
                    mma_f16(acc[mi][n], ah[mi], bh[nj][hf], bh[nj][hf + 2]);
                }
            #pragma unroll
            for (int mi = 0; mi < 4; mi++)
                #pragma unroll
                for (int n = 0; n < 4; n++) {
                    int nj = n >> 1, hf = n & 1;
                    mma_fp8(ac8[mi][n], a8f[mi], b8f[nj][hf], b8f[nj][hf + 2]);
                }
        }
        __syncthreads();
    }

    // epilogue: T = (main + corr*2^-11) * 2^-6 * wl[c,kout]
    const int gid = lane >> 2, tq = lane & 3;
    const int row0 = mt * 128 + warp_m * 64 + gid;
    const int col0 = nt * 128 + warp_n * 32 + tq * 2;
    const float s_corr = 1.0f / 2048.0f;
    const float s_main = 1.0f / 64.0f;
    #pragma unroll
    for (int n = 0; n < 4; n++) {
        int cg = col0 + n * 8;
        float w0 = __ldg(&wl[c * FDIM + cg]) * s_main;
        float w1 = __ldg(&wl[c * FDIM + cg + 1]) * s_main;
        #pragma unroll
        for (int mi = 0; mi < 4; mi++) {
            int r = row0 + mi * 16;
            float* o0 = g_T + ((size_t)c * N_ENT + r) * FDIM + cg;
            float* o1 = g_T + ((size_t)c * N_ENT + r + 8) * FDIM + cg;
            float2 v0 = make_float2((acc[mi][n][0] + ac8[mi][n][0] * s_corr) * w0,
                                    (acc[mi][n][1] + ac8[mi][n][1] * s_corr) * w1);
            float2 v1 = make_float2((acc[mi][n][2] + ac8[mi][n][2] * s_corr) * w0,
                                    (acc[mi][n][3] + ac8[mi][n][3] * s_corr) * w1);
            *(float2*)o0 = v0;
            *(float2*)o1 = v1;
        }
    }
}

// ---------------- gather-dot: out[c,p] = dot(T'_c[i0,:], E[i1,:]) ----------------
__global__ void __launch_bounds__(256) gather_kernel(const int* __restrict__ index,
                                                     const float* __restrict__ emb,
                                                     float* __restrict__ out) {
    int gw = (blockIdx.x * blockDim.x + threadIdx.x) >> 5;
    int lane = threadIdx.x & 31;
    int p0 = gw * 2;
    int c = p0 / PAIRS, p = p0 - c * PAIRS;
    int2 ipA = __ldg((const int2*)index + (size_t)c * PAIRS + p);
    int2 ipB = __ldg((const int2*)index + (size_t)c * PAIRS + p + 1);
    const float4* aA = (const float4*)(g_T + ((size_t)c * N_ENT + ipA.x) * FDIM);
    const float4* bA = (const float4*)(emb + (size_t)ipA.y * FDIM);
    const float4* aB = (const float4*)(g_T + ((size_t)c * N_ENT + ipB.x) * FDIM);
    const float4* bB = (const float4*)(emb + (size_t)ipB.y * FDIM);
    float accA = 0.f, accB = 0.f;
    #pragma unroll
    for (int j = 0; j < 4; j++) {
        float4 xA = __ldg(aA + lane + j * 32);
        float4 yA = __ldg(bA + lane + j * 32);
        float4 xB = __ldg(aB + lane + j * 32);
        float4 yB = __ldg(bB + lane + j * 32);
        accA += xA.x * yA.x + xA.y * yA.y + xA.z * yA.z + xA.w * yA.w;
        accB += xB.x * yB.x + xB.y * yB.y + xB.z * yB.z + xB.w * yB.w;
    }
    #pragma unroll
    for (int o = 16; o; o >>= 1) {
        accA += __shfl_xor_sync(0xffffffffu, accA, o);
        accB += __shfl_xor_sync(0xffffffffu, accB, o);
    }
    if (lane == 0) {
        out[(size_t)c * PAIRS + p]     = accA;
        out[(size_t)c * PAIRS + p + 1] = accB;
    }
}

// ---------------- launch ----------------
extern "C" void kernel_launch(void* const* d_in, const int* in_sizes, int n_in,
                              void* d_out, int out_size) {
    const float* emb   = (const float*)d_in[0];   // [4096, 512] f32
    const int*   index = (const int*)d_in[1];     // [39, 8192, 2] i32
    const float* W     = (const float*)d_in[2];   // [512, 512] f32
    const float* wl    = (const float*)d_in[3];   // [39, 512] f32
    float* out = (float*)d_out;                   // [39, 8192] f32

    cudaFuncSetAttribute(gemm_kernel, cudaFuncAttributeMaxDynamicSharedMemorySize, GEMM_SMEM);

    prep_E<<<1024, 256>>>(emb);
    prep_B<<<dim3(FDIM / 32, FDIM / 32), dim3(32, 32)>>>(W, wl);
    gemm_kernel<<<dim3(N_ENT / 128, FDIM / 128, CELLS), 256, GEMM_SMEM>>>(wl);
    gather_kernel<<<(CELLS * PAIRS) / 16, 256>>>(index, emb, out);
}